// round 1
// baseline (speedup 1.0000x reference)
#include <cuda_runtime.h>
#include <math.h>

#define T_LEN 1024
#define MM 2
#define NN (T_LEN - MM)   /* 1022 templates */
#define RR 0.2f

// per-signal entropies: [0..63] predictions, [64..127] targets
__device__ float g_ent[128];

__global__ __launch_bounds__(512, 1)
void sampen_kernel(const float* __restrict__ pred, const float* __restrict__ tgt) {
    // padded so the sliding-window prefetch xs[j+3] never reads OOB
    __shared__ float xs[T_LEN + 8];
    __shared__ double red[16];
    __shared__ unsigned int redc[16], redc1[16];
    __shared__ double s_mean, s_inv;

    const int s   = blockIdx.x;
    const int tid = threadIdx.x;
    const float* src = (s < 64) ? (pred + (size_t)s * T_LEN)
                                : (tgt  + (size_t)(s - 64) * T_LEN);

    // ---- load signal (2 elements per thread) ----
    float v0 = src[tid];
    float v1 = src[tid + 512];
    xs[tid]       = v0;
    xs[tid + 512] = v1;
    if (tid < 8) xs[T_LEN + tid] = 0.0f;   // pad

    // ---- mean (double) ----
    double lsum = (double)v0 + (double)v1;
    #pragma unroll
    for (int o = 16; o > 0; o >>= 1)
        lsum += __shfl_down_sync(0xffffffffu, lsum, o);
    if ((tid & 31) == 0) red[tid >> 5] = lsum;
    __syncthreads();
    if (tid == 0) {
        double tot = 0.0;
        #pragma unroll
        for (int w = 0; w < 16; w++) tot += red[w];
        s_mean = tot / (double)T_LEN;
    }
    __syncthreads();
    const double mean = s_mean;

    // ---- std (ddof=1, double) ----
    double d0v = (double)v0 - mean;
    double d1v = (double)v1 - mean;
    double lss = d0v * d0v + d1v * d1v;
    #pragma unroll
    for (int o = 16; o > 0; o >>= 1)
        lss += __shfl_down_sync(0xffffffffu, lss, o);
    __syncthreads();               // red[] reuse barrier
    if ((tid & 31) == 0) red[tid >> 5] = lss;
    __syncthreads();
    if (tid == 0) {
        double tot = 0.0;
        #pragma unroll
        for (int w = 0; w < 16; w++) tot += red[w];
        double sd = sqrt(tot / (double)(T_LEN - 1));
        s_inv = 1.0 / (sd + 1e-8);
    }
    __syncthreads();
    const double inv = s_inv;

    // ---- normalize in place ----
    xs[tid]       = (float)(((double)v0 - mean) * inv);
    xs[tid + 512] = (float)(((double)v1 - mean) * inv);
    __syncthreads();

    // ---- pair counting over the upper triangle ----
    // dist matrices are symmetric, diagonal = 0 (always <= R):
    //   matches = NN + 2 * upper_count
    // Load balance: thread t handles rows {t, 1021-t}: combined ~1021 pairs.
    unsigned int cm = 0, cm1 = 0;
    if (tid < (NN - 1) / 2 + 1) {          // tid < 511
        int rows0 = tid;
        int rows1 = (NN - 1) - tid;        // 1021 - tid
        #pragma unroll
        for (int rsel = 0; rsel < 2; rsel++) {
            const int i = rsel ? rows1 : rows0;
            const float xi0 = xs[i];
            const float xi1 = xs[i + 1];
            const float xi2 = xs[i + 2];
            int j = i + 1;
            float a0 = xs[j];
            float a1 = xs[j + 1];
            float a2 = xs[j + 2];
            #pragma unroll 4
            for (; j < NN; j++) {
                float e0 = fabsf(xi0 - a0);
                float e1 = fabsf(xi1 - a1);
                float e2 = fabsf(xi2 - a2);
                float m  = fmaxf(e0, e1);
                float m1 = fmaxf(m, e2);
                cm  += (m  <= RR);
                cm1 += (m1 <= RR);
                a0 = a1; a1 = a2;
                a2 = xs[j + 3];            // pad makes this safe at j = NN-1
            }
        }
    }

    // ---- reduce counts ----
    #pragma unroll
    for (int o = 16; o > 0; o >>= 1) {
        cm  += __shfl_down_sync(0xffffffffu, cm,  o);
        cm1 += __shfl_down_sync(0xffffffffu, cm1, o);
    }
    if ((tid & 31) == 0) { redc[tid >> 5] = cm; redc1[tid >> 5] = cm1; }
    __syncthreads();
    if (tid == 0) {
        unsigned int tm = 0, tm1 = 0;
        #pragma unroll
        for (int w = 0; w < 16; w++) { tm += redc[w]; tm1 += redc1[w]; }
        unsigned int matches_m  = (unsigned int)NN + 2u * tm;
        unsigned int matches_m1 = (unsigned int)NN + 2u * tm1;
        float ratio = (float)matches_m1 / (float)(matches_m > 0u ? matches_m : 1u);
        ratio = fmaxf(ratio, 1e-30f);
        float ent = -logf(ratio);
        // matches_m, matches_m1 >= NN > 0 always, so the where() is always true
        g_ent[s] = ent;
    }
}

__global__ void finalize_kernel(float* __restrict__ out) {
    const int t = threadIdx.x;   // 64 threads
    float d = g_ent[t] - g_ent[64 + t];
    float v = d * d;
    #pragma unroll
    for (int o = 16; o > 0; o >>= 1)
        v += __shfl_down_sync(0xffffffffu, v, o);
    __shared__ float part[2];
    if ((t & 31) == 0) part[t >> 5] = v;
    __syncthreads();
    if (t == 0) out[0] = (part[0] + part[1]) * (1.0f / 64.0f);
}

extern "C" void kernel_launch(void* const* d_in, const int* in_sizes, int n_in,
                              void* d_out, int out_size) {
    const float* pred = (const float*)d_in[0];
    const float* tgt  = (const float*)d_in[1];
    float* out = (float*)d_out;
    sampen_kernel<<<128, 512>>>(pred, tgt);
    finalize_kernel<<<1, 64>>>(out);
}

// round 2
// speedup vs baseline: 1.5251x; 1.5251x over previous
#include <cuda_runtime.h>
#include <math.h>

#define T_LEN 1024
#define NN    1022            /* templates */
#define PAD   1088            /* xs padded: max read index 1084 */
#define RR    0.2f

__device__ float g_ent[128];
__device__ unsigned int g_barrier;

// Build 32 booleans b_k = (|x[k]-x[k+d]| <= Rs) for k in [k0, k0+32).
// xa reads are warp-uniform (broadcast LDS.128); xb reads coalesced LDS.32.
// 4 partial masks break the @P LOP3 dependency chain.
__device__ __forceinline__ unsigned int chunk_mask(const float* __restrict__ xs,
                                                   int k0, int d, float Rs) {
    unsigned int b0 = 0, b1 = 0, b2 = 0, b3 = 0;
    const float* __restrict__ xb = xs + k0 + d;
    #pragma unroll
    for (int q = 0; q < 8; q++) {
        float4 a = *reinterpret_cast<const float4*>(xs + k0 + 4 * q);
        float t0 = xb[4 * q + 0];
        float t1 = xb[4 * q + 1];
        float t2 = xb[4 * q + 2];
        float t3 = xb[4 * q + 3];
        if (fabsf(a.x - t0) <= Rs) b0 |= (1u << (4 * q + 0));
        if (fabsf(a.y - t1) <= Rs) b1 |= (1u << (4 * q + 1));
        if (fabsf(a.z - t2) <= Rs) b2 |= (1u << (4 * q + 2));
        if (fabsf(a.w - t3) <= Rs) b3 |= (1u << (4 * q + 3));
    }
    return (b0 | b1) | (b2 | b3);
}

// Count matches along diagonal d (pairs (k, k+d), k in [0, L)):
//   cm  += popc over k of b_k & b_{k+1}
//   cm1 += popc over k of b_k & b_{k+1} & b_{k+2}
__device__ __forceinline__ void count_diag(const float* __restrict__ xs, int d, float Rs,
                                           unsigned int& cm, unsigned int& cm1) {
    const int L = NN - d;
    unsigned int Bc = chunk_mask(xs, 0, d, Rs);
    for (int c = 0; c * 32 < L; c++) {
        unsigned int Bn = chunk_mask(xs, 32 * (c + 1), d, Rs);
        unsigned int S1 = __funnelshift_r(Bc, Bn, 1);
        unsigned int S2 = __funnelshift_r(Bc, Bn, 2);
        unsigned int mm  = Bc & S1;
        unsigned int mm1 = mm & S2;
        int rem = L - 32 * c;
        unsigned int mask = (rem >= 32) ? 0xffffffffu : ((1u << rem) - 1u);
        cm  += __popc(mm  & mask);
        cm1 += __popc(mm1 & mask);
        Bc = Bn;
    }
}

__global__ __launch_bounds__(512, 1)
void sampen_kernel(const float* __restrict__ pred, const float* __restrict__ tgt,
                   float* __restrict__ out) {
    __shared__ __align__(16) float xs[PAD];
    __shared__ double redA[16], redB[16];
    __shared__ unsigned int redc[16], redc1[16];
    __shared__ float s_thresh;

    const int s   = blockIdx.x;
    const int tid = threadIdx.x;
    const float* src = (s < 64) ? (pred + (size_t)s * T_LEN)
                                : (tgt  + (size_t)(s - 64) * T_LEN);

    // ---- load raw signal + pad ----
    float v0 = src[tid];
    float v1 = src[tid + 512];
    xs[tid]       = v0;
    xs[tid + 512] = v1;
    for (int i = T_LEN + tid; i < PAD; i += 512) xs[i] = 0.0f;

    // ---- std (ddof=1) in double; mean cancels in |xi-xj|, so we only
    //      need a scaled threshold: Rs = R * (std + eps) ----
    double ls  = (double)v0 + (double)v1;
    double ls2 = (double)v0 * (double)v0 + (double)v1 * (double)v1;
    #pragma unroll
    for (int o = 16; o > 0; o >>= 1) {
        ls  += __shfl_down_sync(0xffffffffu, ls,  o);
        ls2 += __shfl_down_sync(0xffffffffu, ls2, o);
    }
    if ((tid & 31) == 0) { redA[tid >> 5] = ls; redB[tid >> 5] = ls2; }
    __syncthreads();
    if (tid == 0) {
        double S = 0.0, S2 = 0.0;
        #pragma unroll
        for (int w = 0; w < 16; w++) { S += redA[w]; S2 += redB[w]; }
        double var = (S2 - S * S / (double)T_LEN) / (double)(T_LEN - 1);
        double sd  = sqrt(var);
        s_thresh = (float)((double)RR * (sd + 1e-8));
    }
    __syncthreads();
    const float Rs = s_thresh;

    // ---- upper-triangle counting by diagonals ----
    // thread t: diagonals d = t+1 and d = 1021-t  (lengths sum to 1022)
    unsigned int cm = 0, cm1 = 0;
    if (tid < 511) {
        int dA = tid + 1;
        int dB = 1021 - tid;
        count_diag(xs, dA, Rs, cm, cm1);
        if (dB != dA) count_diag(xs, dB, Rs, cm, cm1);
    }

    // ---- reduce counts ----
    #pragma unroll
    for (int o = 16; o > 0; o >>= 1) {
        cm  += __shfl_down_sync(0xffffffffu, cm,  o);
        cm1 += __shfl_down_sync(0xffffffffu, cm1, o);
    }
    if ((tid & 31) == 0) { redc[tid >> 5] = cm; redc1[tid >> 5] = cm1; }
    __syncthreads();

    if (tid == 0) {
        unsigned int tm = 0, tm1 = 0;
        #pragma unroll
        for (int w = 0; w < 16; w++) { tm += redc[w]; tm1 += redc1[w]; }
        // symmetric matrix + zero diagonal: matches = NN + 2*upper
        unsigned int matches_m  = (unsigned int)NN + 2u * tm;
        unsigned int matches_m1 = (unsigned int)NN + 2u * tm1;
        float ratio = (float)matches_m1 / (float)matches_m;   // matches_m >= NN > 0
        ratio = fmaxf(ratio, 1e-30f);
        g_ent[s] = -logf(ratio);

        // ---- fused finalize: last block computes the MSE ----
        __threadfence();
        unsigned int old = atomicAdd(&g_barrier, 1);
        if (old == 127u) {
            g_barrier = 0;            // reset for next graph replay
            __threadfence();          // acquire: make all g_ent writes visible
            float acc = 0.0f;
            #pragma unroll
            for (int i = 0; i < 64; i++) {
                float dp = __ldcg(&g_ent[i]);
                float dt = __ldcg(&g_ent[64 + i]);
                float dd = dp - dt;
                acc += dd * dd;
            }
            out[0] = acc * (1.0f / 64.0f);
        }
    }
}

extern "C" void kernel_launch(void* const* d_in, const int* in_sizes, int n_in,
                              void* d_out, int out_size) {
    const float* pred = (const float*)d_in[0];
    const float* tgt  = (const float*)d_in[1];
    float* out = (float*)d_out;
    sampen_kernel<<<128, 512>>>(pred, tgt, out);
}

// round 3
// speedup vs baseline: 1.6465x; 1.0795x over previous
#include <cuda_runtime.h>
#include <math.h>

#define T_LEN 1024
#define NN    1022            /* templates */
#define PAD   1096            /* max smem read index is 1090 */
#define RR    0.2f

__device__ float g_ent[128];
__device__ unsigned int g_barrier;

// Masks for one 32-k chunk of 4 consecutive diagonals dbase..dbase+3 (dbase ≡ 1 mod 4).
// bit k of m[s] = ( |xs[k0+k] - xs[k0+k+dbase+s]| <= Rs )
__device__ __forceinline__ void chunk_mask4(const float* __restrict__ xs, int k0, int dbase,
                                            float Rs, unsigned int m[4]) {
    const float4* __restrict__ xa4 = reinterpret_cast<const float4*>(xs + k0);
    const float4* __restrict__ w4  = reinterpret_cast<const float4*>(xs + k0 + dbase - 1);
    unsigned int accA[4] = {0, 0, 0, 0};
    unsigned int accB[4] = {0, 0, 0, 0};
    float w[8];
    float4 t0 = w4[0];
    w[0] = t0.x; w[1] = t0.y; w[2] = t0.z; w[3] = t0.w;
    #pragma unroll
    for (int q = 0; q < 8; q++) {
        float4 a  = xa4[q];
        float4 tn = w4[q + 1];
        w[4] = tn.x; w[5] = tn.y; w[6] = tn.z; w[7] = tn.w;
        float av[4] = {a.x, a.y, a.z, a.w};
        #pragma unroll
        for (int s = 0; s < 4; s++) {
            #pragma unroll
            for (int r = 0; r < 4; r++) {
                unsigned int bit = 1u << (4 * q + r);
                if (fabsf(av[r] - w[1 + s + r]) <= Rs) {
                    if (q & 1) accB[s] |= bit; else accA[s] |= bit;
                }
            }
        }
        w[0] = w[4]; w[1] = w[5]; w[2] = w[6]; w[3] = w[7];
    }
    #pragma unroll
    for (int s = 0; s < 4; s++) m[s] = accA[s] | accB[s];
}

// Count m/m1 matches for chunks [c0, c1) of the 4 diagonals dbase..dbase+3.
// Diagonal s has Lbase - s valid template pairs.
__device__ __forceinline__ void process_range(const float* __restrict__ xs,
                                              int dbase, int Lbase, int c0, int c1, float Rs,
                                              unsigned int& cm, unsigned int& cm1) {
    if (c0 >= c1) return;
    unsigned int Bc[4], Bn[4];
    chunk_mask4(xs, 32 * c0, dbase, Rs, Bc);
    for (int c = c0; c < c1; c++) {
        chunk_mask4(xs, 32 * (c + 1), dbase, Rs, Bn);
        if (32 * c + 35 <= Lbase) {          // all 4 diagonals full in this chunk
            #pragma unroll
            for (int s = 0; s < 4; s++) {
                unsigned int S1 = __funnelshift_r(Bc[s], Bn[s], 1);
                unsigned int S2 = __funnelshift_r(Bc[s], Bn[s], 2);
                unsigned int mm = Bc[s] & S1;
                cm  += __popc(mm);
                cm1 += __popc(mm & S2);
            }
        } else {                              // diagonal-end chunk: mask the tail
            #pragma unroll
            for (int s = 0; s < 4; s++) {
                int rem = Lbase - s - 32 * c;
                unsigned int mask = (rem >= 32) ? 0xffffffffu
                                  : ((rem <= 0) ? 0u : ((1u << rem) - 1u));
                unsigned int S1 = __funnelshift_r(Bc[s], Bn[s], 1);
                unsigned int S2 = __funnelshift_r(Bc[s], Bn[s], 2);
                unsigned int mm = Bc[s] & S1 & mask;
                cm  += __popc(mm);
                cm1 += __popc(mm & S2);
            }
        }
        Bc[0] = Bn[0]; Bc[1] = Bn[1]; Bc[2] = Bn[2]; Bc[3] = Bn[3];
    }
}

__global__ __launch_bounds__(1024, 1)
void sampen_kernel(const float* __restrict__ pred, const float* __restrict__ tgt,
                   float* __restrict__ out) {
    __shared__ __align__(16) float xs[PAD];
    __shared__ double redA[32], redB[32];
    __shared__ unsigned int redc[32], redc1[32];
    __shared__ float s_thresh;

    const int s   = blockIdx.x;
    const int tid = threadIdx.x;
    const float* src = (s < 64) ? (pred + (size_t)s * T_LEN)
                                : (tgt  + (size_t)(s - 64) * T_LEN);

    // ---- load raw signal + zero pad ----
    float v = src[tid];
    xs[tid] = v;
    for (int i = T_LEN + tid; i < PAD; i += 1024) xs[i] = 0.0f;

    // ---- std (ddof=1) in double; mean cancels inside |xi-xj|, so we only
    //      need a scaled threshold: Rs = R * (std + eps) ----
    double ls  = (double)v;
    double ls2 = (double)v * (double)v;
    #pragma unroll
    for (int o = 16; o > 0; o >>= 1) {
        ls  += __shfl_down_sync(0xffffffffu, ls,  o);
        ls2 += __shfl_down_sync(0xffffffffu, ls2, o);
    }
    if ((tid & 31) == 0) { redA[tid >> 5] = ls; redB[tid >> 5] = ls2; }
    __syncthreads();
    if (tid == 0) {
        double S = 0.0, S2 = 0.0;
        #pragma unroll
        for (int w = 0; w < 32; w++) { S += redA[w]; S2 += redB[w]; }
        double var = (S2 - S * S / (double)T_LEN) / (double)(T_LEN - 1);
        double sd  = sqrt(var);
        s_thresh = (float)((double)RR * (sd + 1e-8));
    }
    __syncthreads();
    const float Rs = s_thresh;

    // ---- upper-triangle counting: 4-diagonal groups, paired + 8-way split-k ----
    // Group g covers diagonals 4g+1..4g+4 (g in [0,256); overflow diagonals auto-mask).
    // Pair (P, 255-P); total chunk count C_A + C_B == 33 for every P.
    // Thread = (P = tid & 127, slot = tid >> 7); slot carves [g0, g1) of the 33 chunks.
    const int P  = tid & 127;
    const int sg = tid >> 7;
    const int dA = 4 * P + 1;
    const int LA = NN - dA;            // 1021 - 4P
    const int dB = 1021 - 4 * P;       // group 255-P
    const int LB = NN - dB;            // 4P + 1
    const int CA = (LA + 31) >> 5;
    const int CB = (LB + 31) >> 5;
    const int C  = CA + CB;            // == 33
    const int g0 = (sg * C) >> 3;
    const int g1 = ((sg + 1) * C) >> 3;

    unsigned int cm = 0, cm1 = 0;
    {
        int a0 = g0, a1 = (g1 < CA) ? g1 : CA;
        process_range(xs, dA, LA, a0, a1, Rs, cm, cm1);
        int b0 = (g0 > CA ? g0 : CA) - CA;
        int b1 = g1 - CA;
        process_range(xs, dB, LB, b0, b1, Rs, cm, cm1);
    }

    // ---- reduce counts ----
    #pragma unroll
    for (int o = 16; o > 0; o >>= 1) {
        cm  += __shfl_down_sync(0xffffffffu, cm,  o);
        cm1 += __shfl_down_sync(0xffffffffu, cm1, o);
    }
    if ((tid & 31) == 0) { redc[tid >> 5] = cm; redc1[tid >> 5] = cm1; }
    __syncthreads();

    if (tid == 0) {
        unsigned int tm = 0, tm1 = 0;
        #pragma unroll
        for (int w = 0; w < 32; w++) { tm += redc[w]; tm1 += redc1[w]; }
        // symmetric matrix + zero diagonal: matches = NN + 2*upper
        unsigned int matches_m  = (unsigned int)NN + 2u * tm;
        unsigned int matches_m1 = (unsigned int)NN + 2u * tm1;
        float ratio = (float)matches_m1 / (float)matches_m;   // matches_m >= NN > 0
        ratio = fmaxf(ratio, 1e-30f);
        g_ent[s] = -logf(ratio);

        // ---- fused finalize: last block computes the MSE ----
        __threadfence();
        unsigned int old = atomicAdd(&g_barrier, 1);
        if (old == 127u) {
            g_barrier = 0;            // reset for next graph replay
            __threadfence();          // make all g_ent writes visible
            float acc = 0.0f;
            #pragma unroll
            for (int i = 0; i < 64; i++) {
                float dp = __ldcg(&g_ent[i]);
                float dt = __ldcg(&g_ent[64 + i]);
                float dd = dp - dt;
                acc += dd * dd;
            }
            out[0] = acc * (1.0f / 64.0f);
        }
    }
}

extern "C" void kernel_launch(void* const* d_in, const int* in_sizes, int n_in,
                              void* d_out, int out_size) {
    const float* pred = (const float*)d_in[0];
    const float* tgt  = (const float*)d_in[1];
    float* out = (float*)d_out;
    sampen_kernel<<<128, 1024>>>(pred, tgt, out);
}